// round 2
// baseline (speedup 1.0000x reference)
#include <cuda_runtime.h>
#include <math_constants.h>

// ---------------- scratch (no allocation allowed; static device globals) ----
__device__ float d_dist[16 * 1024 * 1024];   // per-layer pairwise scores (64MB)
__device__ float d_sq  [16 * 1024];          // per-point squared norms
__device__ int   d_idx [16 * 1024 * 40];     // top-40 neighbor indices
__device__ float d_pq  [16 * 1024 * 512];    // [p | q] projections (32MB)
__device__ float d_cat [16 * 1024 * 512];    // concatenated layer outputs (32MB)
__device__ float d_y   [16 * 1024 * 1024];   // final pre-max logits (64MB)
__device__ float d_wpq [512 * 128];          // transformed weights [w_L ; w_R-w_L]

static __device__ __forceinline__ unsigned long long u64max(unsigned long long a,
                                                            unsigned long long b) {
    return a > b ? a : b;
}

// ---------------- generic tiled SGEMM: C = A(MxK) * B(NxK)^T ----------------
// mode 0: plain.  mode 1 (distance): C = (2*acc - sq[row]) - sq[col], batched.
__global__ void sgemm_kernel(const float* __restrict__ A, int lda, long long sA,
                             const float* __restrict__ B, int ldb, long long sB,
                             const float* __restrict__ sq,
                             float* __restrict__ C, int ldc, long long sC,
                             int M, int N, int K, int mode)
{
    int bz = blockIdx.z;
    A += (long long)bz * sA;
    B += (long long)bz * sB;
    C += (long long)bz * sC;
    const float* sqb = sq ? (sq + (long long)bz * M) : nullptr;

    __shared__ float As[16][64];
    __shared__ float Bs[16][64];

    int tid = threadIdx.x;            // 256 threads
    int tx = tid & 15, ty = tid >> 4; // 16x16, 4x4 per thread
    int row0 = blockIdx.x * 64;
    int col0 = blockIdx.y * 64;

    int lr = tid >> 2;                // 0..63
    int lk = (tid & 3) * 4;           // 0,4,8,12

    float acc[4][4];
#pragma unroll
    for (int i = 0; i < 4; i++)
#pragma unroll
        for (int j = 0; j < 4; j++) acc[i][j] = 0.f;

    for (int k0 = 0; k0 < K; k0 += 16) {
#pragma unroll
        for (int i = 0; i < 4; i++) {
            int k = k0 + lk + i;
            As[lk + i][lr] = (k < K) ? A[(long long)(row0 + lr) * lda + k] : 0.f;
            Bs[lk + i][lr] = (k < K) ? B[(long long)(col0 + lr) * ldb + k] : 0.f;
        }
        __syncthreads();
#pragma unroll
        for (int kk = 0; kk < 16; kk++) {
            float4 a = *(const float4*)&As[kk][ty * 4];
            float4 b = *(const float4*)&Bs[kk][tx * 4];
            acc[0][0] += a.x * b.x; acc[0][1] += a.x * b.y; acc[0][2] += a.x * b.z; acc[0][3] += a.x * b.w;
            acc[1][0] += a.y * b.x; acc[1][1] += a.y * b.y; acc[1][2] += a.y * b.z; acc[1][3] += a.y * b.w;
            acc[2][0] += a.z * b.x; acc[2][1] += a.z * b.y; acc[2][2] += a.z * b.z; acc[2][3] += a.z * b.w;
            acc[3][0] += a.w * b.x; acc[3][1] += a.w * b.y; acc[3][2] += a.w * b.z; acc[3][3] += a.w * b.w;
        }
        __syncthreads();
    }

#pragma unroll
    for (int i = 0; i < 4; i++) {
        int r = row0 + ty * 4 + i;
#pragma unroll
        for (int j = 0; j < 4; j++) {
            int c = col0 + tx * 4 + j;
            float v = acc[i][j];
            if (mode == 1) v = (2.f * v - sqb[r]) - sqb[c];
            C[(long long)r * ldc + c] = v;
        }
    }
}

// ---------------- squared norms: one warp per point --------------------------
__global__ void sq_kernel(const float* __restrict__ H, int lda, int C,
                          float* __restrict__ SQ)
{
    int gwarp = (blockIdx.x * blockDim.x + threadIdx.x) >> 5;
    int lane = threadIdx.x & 31;
    if (gwarp >= 16 * 1024) return;
    const float* h = H + (long long)gwarp * lda;
    float s = 0.f;
    for (int c = lane; c < C; c += 32) { float v = h[c]; s += v * v; }
#pragma unroll
    for (int d = 16; d > 0; d >>= 1) s += __shfl_down_sync(0xffffffffu, s, d);
    if (lane == 0) SQ[gwarp] = s;
}

// ---------------- top-40 by iterative block argmax (ties -> lower index) ----
__global__ void topk40_kernel(const float* __restrict__ S, int* __restrict__ IDX)
{
    int row = blockIdx.x;                  // 0..16383
    const float* s = S + (long long)row * 1024;
    int tid = threadIdx.x;                 // 256 threads, 4 values each
    unsigned long long key[4];
#pragma unroll
    for (int j = 0; j < 4; j++) {
        int m = tid + j * 256;
        unsigned u = __float_as_uint(s[m]);
        u = (u & 0x80000000u) ? ~u : (u | 0x80000000u);   // order-preserving map
        key[j] = ((unsigned long long)u << 32) | (unsigned)(2047 - m);
    }
    __shared__ unsigned long long wmax[8];
    __shared__ int winner;
    int lane = tid & 31, wid = tid >> 5;

    for (int it = 0; it < 40; it++) {
        unsigned long long best = key[0];
#pragma unroll
        for (int j = 1; j < 4; j++) best = u64max(best, key[j]);
#pragma unroll
        for (int d = 16; d > 0; d >>= 1)
            best = u64max(best, __shfl_down_sync(0xffffffffu, best, d));
        if (lane == 0) wmax[wid] = best;
        __syncthreads();
        if (tid == 0) {
            unsigned long long b = wmax[0];
#pragma unroll
            for (int w = 1; w < 8; w++) b = u64max(b, wmax[w]);
            int m = 2047 - (int)(b & 0xFFFFFFFFull);
            winner = m;
            IDX[row * 40 + it] = m;
        }
        __syncthreads();
        int m = winner;
        if ((m & 255) == tid) key[m >> 8] = 0ull;   // remove winner
    }
}

// ---------------- weight transform: [w_L ; w_R - w_L] ------------------------
__global__ void wprep_kernel(const float* __restrict__ W, float* __restrict__ WPQ,
                             int Co, int C)
{
    int i = blockIdx.x * blockDim.x + threadIdx.x;
    if (i >= Co * C) return;
    int o = i / C, c = i % C;
    float wl = W[o * 2 * C + c];
    float wr = W[o * 2 * C + C + c];
    WPQ[o * C + c] = wl;
    WPQ[(Co + o) * C + c] = wr - wl;
}

// ---------------- gather-max + BN affine + LeakyReLU -------------------------
__global__ void edge_gathermax(const float* __restrict__ PQ,     // [16384][2*Co]
                               const int* __restrict__ IDX,
                               const float* __restrict__ g,
                               const float* __restrict__ bb,
                               float* __restrict__ OUT,          // cat + offset
                               int Co, int ldo)
{
    const float BN_INV = 0.9999950000374997f;  // 1/sqrt(1+1e-5)
    int pt = blockIdx.x;                       // 0..16383
    int b = pt >> 10;
    __shared__ int nb[40];
    if (threadIdx.x < 40) nb[threadIdx.x] = IDX[pt * 40 + threadIdx.x];
    __syncthreads();
    int ld = 2 * Co;
    long long bbase = (long long)(b << 10) * ld;
    for (int o = threadIdx.x; o < Co; o += blockDim.x) {
        float mx = -CUDART_INF_F, mn = CUDART_INF_F;
#pragma unroll 8
        for (int k = 0; k < 40; k++) {
            float v = PQ[bbase + (long long)nb[k] * ld + o];
            mx = fmaxf(mx, v);
            mn = fminf(mn, v);
        }
        float q  = PQ[(long long)pt * ld + Co + o];
        float gg = g[o];
        float y = (gg >= 0.f ? mx : mn) + q;     // monotone transform commutes
        y = gg * (y * BN_INV) + bb[o];
        y = y > 0.f ? y : 0.2f * y;
        OUT[(long long)pt * ldo + o] = y;
    }
}

// ---------------- final max over N (+ bias, constant over n) -----------------
__global__ void maxn_kernel(const float* __restrict__ Y, const float* __restrict__ bf,
                            float* __restrict__ OUT)
{
    int b = blockIdx.y;
    int o = blockIdx.x * blockDim.x + threadIdx.x;   // 0..1023
    const float* y = Y + ((long long)b * 1024) * 1024 + o;
    float mx = -CUDART_INF_F;
    for (int n = 0; n < 1024; n++) mx = fmaxf(mx, y[(long long)n * 1024]);
    OUT[b * 1024 + o] = mx + bf[o];
}

// ---------------- launch -----------------------------------------------------
extern "C" void kernel_launch(void* const* d_in, const int* in_sizes, int n_in,
                              void* d_out, int out_size)
{
    (void)in_sizes; (void)n_in; (void)out_size;
    const float* x  = (const float*)d_in[0];
    const float* w[4]  = {(const float*)d_in[1], (const float*)d_in[4],
                          (const float*)d_in[7], (const float*)d_in[10]};
    const float* g[4]  = {(const float*)d_in[2], (const float*)d_in[5],
                          (const float*)d_in[8], (const float*)d_in[11]};
    const float* bb[4] = {(const float*)d_in[3], (const float*)d_in[6],
                          (const float*)d_in[9], (const float*)d_in[12]};
    const float* wf = (const float*)d_in[13];
    const float* bf = (const float*)d_in[14];
    float* out = (float*)d_out;

    float *dist, *sq, *pq, *cat, *yb, *wpq; int* idx;
    cudaGetSymbolAddress((void**)&dist, d_dist);
    cudaGetSymbolAddress((void**)&sq,   d_sq);
    cudaGetSymbolAddress((void**)&idx,  d_idx);
    cudaGetSymbolAddress((void**)&pq,   d_pq);
    cudaGetSymbolAddress((void**)&cat,  d_cat);
    cudaGetSymbolAddress((void**)&yb,   d_y);
    cudaGetSymbolAddress((void**)&wpq,  d_wpq);

    const int Cs[4]   = {3, 64, 64, 128};
    const int Cos[4]  = {64, 64, 128, 256};
    const int offs[4] = {0, 64, 128, 256};  // output column offsets in cat

    for (int l = 0; l < 4; l++) {
        int C = Cs[l], Co = Cos[l];
        const float* A;
        int lda;
        if (l == 0) { A = x; lda = 3; }
        else        { A = cat + offs[l - 1]; lda = 512; }

        // 1. per-point squared norms
        sq_kernel<<<2048, 256>>>(A, lda, C, sq);
        // 2. batched pairwise score GEMM: s = 2*h.h^T - sq_n - sq_m
        sgemm_kernel<<<dim3(16, 16, 16), 256>>>(
            A, lda, 1024LL * lda, A, lda, 1024LL * lda, sq,
            dist, 1024, 1024LL * 1024, 1024, 1024, C, 1);
        // 3. top-40 per row
        topk40_kernel<<<16384, 256>>>(dist, idx);
        // 4. weight transform
        wprep_kernel<<<(Co * C + 255) / 256, 256>>>(w[l], wpq, Co, C);
        // 5. per-point projections [p | q] = h * [w_L ; w_R-w_L]^T
        sgemm_kernel<<<dim3(256, (2 * Co) / 64, 1), 256>>>(
            A, lda, 0, wpq, C, 0, nullptr,
            pq, 2 * Co, 0, 16384, 2 * Co, C, 0);
        // 6. gather-max over neighbors + BN + LeakyReLU -> cat slice
        edge_gathermax<<<16384, Co>>>(pq, idx, g[l], bb[l], cat + offs[l], Co, 512);
    }

    // final linear 512 -> 1024 (bias folded into max), then max over N
    sgemm_kernel<<<dim3(256, 16, 1), 256>>>(
        cat, 512, 0, wf, 512, 0, nullptr,
        yb, 1024, 0, 16384, 1024, 512, 0);
    maxn_kernel<<<dim3(8, 16), 128>>>(yb, bf, out);
}

// round 3
// speedup vs baseline: 1.1237x; 1.1237x over previous
#include <cuda_runtime.h>
#include <math_constants.h>

// ---------------- scratch (no allocation allowed; static device globals) ----
__device__ float d_dist[16 * 1024 * 1024];   // per-layer pairwise scores (64MB)
__device__ float d_sq  [16 * 1024];          // per-point squared norms
__device__ int   d_idx [16 * 1024 * 40];     // top-40 neighbor indices
__device__ float d_pq  [16 * 1024 * 512];    // [p | q] projections (32MB)
__device__ float d_cat [16 * 1024 * 512];    // concatenated layer outputs (32MB)
__device__ float d_y   [16 * 1024 * 1024];   // final pre-max logits (64MB)
__device__ float d_wpq [512 * 128];          // transformed weights [w_L ; w_R-w_L]

static __device__ __forceinline__ unsigned long long u64max(unsigned long long a,
                                                            unsigned long long b) {
    return a > b ? a : b;
}

// ---------------- 128x128x8 double-buffered SGEMM: C = A(MxK) * B(NxK)^T ----
// mode 0: plain.  mode 1 (distance): C = (2*acc - sq[row]) - sq[col], batched.
// Requires M % 128 == 0 and N % 128 == 0 (true for all calls here).
__global__ void __launch_bounds__(256, 2)
sgemm128(const float* __restrict__ A, int lda, long long sA,
         const float* __restrict__ B, int ldb, long long sB,
         const float* __restrict__ sq,
         float* __restrict__ C, int ldc, long long sC,
         int M, int N, int K, int mode)
{
    int bz = blockIdx.z;
    A += (long long)bz * sA;
    B += (long long)bz * sB;
    C += (long long)bz * sC;
    const float* sqb = sq ? (sq + (long long)bz * M) : nullptr;

    __shared__ float As[2][8][132];
    __shared__ float Bs[2][8][132];

    const int tid = threadIdx.x;          // 256 threads
    const int row0 = blockIdx.x * 128;
    const int col0 = blockIdx.y * 128;

    // loader: element e = tid + j*256 of the 128x8 tile; k = e&7 (fast), m = e>>3
    const int lk = tid & 7;
    const int lm = tid >> 3;              // 0..31, +32*j

    // compute: 16x16 thread grid, 8x8 microtile
    const int tx = tid & 15;              // col group
    const int ty = tid >> 4;              // row group

    float acc[8][8];
#pragma unroll
    for (int i = 0; i < 8; i++)
#pragma unroll
        for (int j = 0; j < 8; j++) acc[i][j] = 0.f;

    float pa[4], pb[4];
    const int nk = (K + 7) >> 3;

    // prologue: load tile 0
    {
        int k = lk;
        bool ok = (k < K);
#pragma unroll
        for (int j = 0; j < 4; j++) {
            int m = lm + 32 * j;
            pa[j] = ok ? A[(long long)(row0 + m) * lda + k] : 0.f;
            pb[j] = ok ? B[(long long)(col0 + m) * ldb + k] : 0.f;
        }
#pragma unroll
        for (int j = 0; j < 4; j++) {
            As[0][lk][lm + 32 * j] = pa[j];
            Bs[0][lk][lm + 32 * j] = pb[j];
        }
    }
    __syncthreads();

    for (int t = 0; t < nk; t++) {
        int cur = t & 1;
        if (t + 1 < nk) {
            int k = (t + 1) * 8 + lk;
            bool ok = (k < K);
#pragma unroll
            for (int j = 0; j < 4; j++) {
                int m = lm + 32 * j;
                pa[j] = ok ? A[(long long)(row0 + m) * lda + k] : 0.f;
                pb[j] = ok ? B[(long long)(col0 + m) * ldb + k] : 0.f;
            }
        }
#pragma unroll
        for (int kk = 0; kk < 8; kk++) {
            float a[8], b[8];
            *(float4*)&a[0] = *(const float4*)&As[cur][kk][ty * 8];
            *(float4*)&a[4] = *(const float4*)&As[cur][kk][ty * 8 + 4];
            *(float4*)&b[0] = *(const float4*)&Bs[cur][kk][tx * 8];
            *(float4*)&b[4] = *(const float4*)&Bs[cur][kk][tx * 8 + 4];
#pragma unroll
            for (int i = 0; i < 8; i++)
#pragma unroll
                for (int j = 0; j < 8; j++)
                    acc[i][j] += a[i] * b[j];
        }
        if (t + 1 < nk) {
            int nxt = cur ^ 1;
#pragma unroll
            for (int j = 0; j < 4; j++) {
                As[nxt][lk][lm + 32 * j] = pa[j];
                Bs[nxt][lk][lm + 32 * j] = pb[j];
            }
        }
        __syncthreads();
    }

    // epilogue
#pragma unroll
    for (int i = 0; i < 8; i++) {
        int r = row0 + ty * 8 + i;
        float srow = (mode == 1) ? sqb[r] : 0.f;
        float out[8];
#pragma unroll
        for (int j = 0; j < 8; j++) {
            float v = acc[i][j];
            if (mode == 1) v = (2.f * v - srow) - sqb[col0 + tx * 8 + j];
            out[j] = v;
        }
        float* cp = &C[(long long)r * ldc + col0 + tx * 8];
        *(float4*)&cp[0] = *(float4*)&out[0];
        *(float4*)&cp[4] = *(float4*)&out[4];
    }
}

// ---------------- squared norms: one warp per point --------------------------
__global__ void sq_kernel(const float* __restrict__ H, int lda, int C,
                          float* __restrict__ SQ)
{
    int gwarp = (blockIdx.x * blockDim.x + threadIdx.x) >> 5;
    int lane = threadIdx.x & 31;
    if (gwarp >= 16 * 1024) return;
    const float* h = H + (long long)gwarp * lda;
    float s = 0.f;
    for (int c = lane; c < C; c += 32) { float v = h[c]; s += v * v; }
#pragma unroll
    for (int d = 16; d > 0; d >>= 1) s += __shfl_down_sync(0xffffffffu, s, d);
    if (lane == 0) SQ[gwarp] = s;
}

// ---------------- top-40 by iterative block argmax (ties -> lower index) ----
__global__ void topk40_kernel(const float* __restrict__ S, int* __restrict__ IDX)
{
    int row = blockIdx.x;                  // 0..16383
    const float* s = S + (long long)row * 1024;
    int tid = threadIdx.x;                 // 256 threads, 4 values each
    unsigned long long key[4];
#pragma unroll
    for (int j = 0; j < 4; j++) {
        int m = tid + j * 256;
        unsigned u = __float_as_uint(s[m]);
        u = (u & 0x80000000u) ? ~u : (u | 0x80000000u);   // order-preserving map
        key[j] = ((unsigned long long)u << 32) | (unsigned)(2047 - m);
    }
    __shared__ unsigned long long wmax[8];
    __shared__ int winner;
    int lane = tid & 31, wid = tid >> 5;

    for (int it = 0; it < 40; it++) {
        unsigned long long best = key[0];
#pragma unroll
        for (int j = 1; j < 4; j++) best = u64max(best, key[j]);
#pragma unroll
        for (int d = 16; d > 0; d >>= 1)
            best = u64max(best, __shfl_down_sync(0xffffffffu, best, d));
        if (lane == 0) wmax[wid] = best;
        __syncthreads();
        if (tid == 0) {
            unsigned long long b = wmax[0];
#pragma unroll
            for (int w = 1; w < 8; w++) b = u64max(b, wmax[w]);
            int m = 2047 - (int)(b & 0xFFFFFFFFull);
            winner = m;
            IDX[row * 40 + it] = m;
        }
        __syncthreads();
        int m = winner;
        if ((m & 255) == tid) key[m >> 8] = 0ull;   // remove winner
    }
}

// ---------------- weight transform: [w_L ; w_R - w_L] ------------------------
__global__ void wprep_kernel(const float* __restrict__ W, float* __restrict__ WPQ,
                             int Co, int C)
{
    int i = blockIdx.x * blockDim.x + threadIdx.x;
    if (i >= Co * C) return;
    int o = i / C, c = i % C;
    float wl = W[o * 2 * C + c];
    float wr = W[o * 2 * C + C + c];
    WPQ[o * C + c] = wl;
    WPQ[(Co + o) * C + c] = wr - wl;
}

// ---------------- gather-max + BN affine + LeakyReLU -------------------------
__global__ void edge_gathermax(const float* __restrict__ PQ,     // [16384][2*Co]
                               const int* __restrict__ IDX,
                               const float* __restrict__ g,
                               const float* __restrict__ bb,
                               float* __restrict__ OUT,          // cat + offset
                               int Co, int ldo)
{
    const float BN_INV = 0.9999950000374997f;  // 1/sqrt(1+1e-5)
    int pt = blockIdx.x;                       // 0..16383
    int b = pt >> 10;
    __shared__ int nb[40];
    if (threadIdx.x < 40) nb[threadIdx.x] = IDX[pt * 40 + threadIdx.x];
    __syncthreads();
    int ld = 2 * Co;
    long long bbase = (long long)(b << 10) * ld;
    for (int o = threadIdx.x; o < Co; o += blockDim.x) {
        float mx = -CUDART_INF_F, mn = CUDART_INF_F;
#pragma unroll 8
        for (int k = 0; k < 40; k++) {
            float v = PQ[bbase + (long long)nb[k] * ld + o];
            mx = fmaxf(mx, v);
            mn = fminf(mn, v);
        }
        float q  = PQ[(long long)pt * ld + Co + o];
        float gg = g[o];
        float y = (gg >= 0.f ? mx : mn) + q;     // monotone transform commutes
        y = gg * (y * BN_INV) + bb[o];
        y = y > 0.f ? y : 0.2f * y;
        OUT[(long long)pt * ldo + o] = y;
    }
}

// ---------------- final max over N (+ bias, constant over n) -----------------
__global__ void maxn_kernel(const float* __restrict__ Y, const float* __restrict__ bf,
                            float* __restrict__ OUT)
{
    int b = blockIdx.y;
    int o = blockIdx.x * blockDim.x + threadIdx.x;   // 0..1023
    const float* y = Y + ((long long)b * 1024) * 1024 + o;
    float mx = -CUDART_INF_F;
    for (int n = 0; n < 1024; n++) mx = fmaxf(mx, y[(long long)n * 1024]);
    OUT[b * 1024 + o] = mx + bf[o];
}

// ---------------- launch -----------------------------------------------------
extern "C" void kernel_launch(void* const* d_in, const int* in_sizes, int n_in,
                              void* d_out, int out_size)
{
    (void)in_sizes; (void)n_in; (void)out_size;
    const float* x  = (const float*)d_in[0];
    const float* w[4]  = {(const float*)d_in[1], (const float*)d_in[4],
                          (const float*)d_in[7], (const float*)d_in[10]};
    const float* g[4]  = {(const float*)d_in[2], (const float*)d_in[5],
                          (const float*)d_in[8], (const float*)d_in[11]};
    const float* bb[4] = {(const float*)d_in[3], (const float*)d_in[6],
                          (const float*)d_in[9], (const float*)d_in[12]};
    const float* wf = (const float*)d_in[13];
    const float* bf = (const float*)d_in[14];
    float* out = (float*)d_out;

    float *dist, *sq, *pq, *cat, *yb, *wpq; int* idx;
    cudaGetSymbolAddress((void**)&dist, d_dist);
    cudaGetSymbolAddress((void**)&sq,   d_sq);
    cudaGetSymbolAddress((void**)&idx,  d_idx);
    cudaGetSymbolAddress((void**)&pq,   d_pq);
    cudaGetSymbolAddress((void**)&cat,  d_cat);
    cudaGetSymbolAddress((void**)&yb,   d_y);
    cudaGetSymbolAddress((void**)&wpq,  d_wpq);

    const int Cs[4]   = {3, 64, 64, 128};
    const int Cos[4]  = {64, 64, 128, 256};
    const int offs[4] = {0, 64, 128, 256};  // output column offsets in cat

    for (int l = 0; l < 4; l++) {
        int C = Cs[l], Co = Cos[l];
        const float* A;
        int lda;
        if (l == 0) { A = x; lda = 3; }
        else        { A = cat + offs[l - 1]; lda = 512; }

        // 1. per-point squared norms
        sq_kernel<<<2048, 256>>>(A, lda, C, sq);
        // 2. batched pairwise score GEMM: s = 2*h.h^T - sq_n - sq_m
        sgemm128<<<dim3(8, 8, 16), 256>>>(
            A, lda, 1024LL * lda, A, lda, 1024LL * lda, sq,
            dist, 1024, 1024LL * 1024, 1024, 1024, C, 1);
        // 3. top-40 per row
        topk40_kernel<<<16384, 256>>>(dist, idx);
        // 4. weight transform
        wprep_kernel<<<(Co * C + 255) / 256, 256>>>(w[l], wpq, Co, C);
        // 5. per-point projections [p | q] = h * [w_L ; w_R-w_L]^T
        sgemm128<<<dim3(128, (2 * Co) / 128, 1), 256>>>(
            A, lda, 0, wpq, C, 0, nullptr,
            pq, 2 * Co, 0, 16384, 2 * Co, C, 0);
        // 6. gather-max over neighbors + BN + LeakyReLU -> cat slice
        edge_gathermax<<<16384, Co>>>(pq, idx, g[l], bb[l], cat + offs[l], Co, 512);
    }

    // final linear 512 -> 1024 (bias folded into max), then max over N
    sgemm128<<<dim3(128, 8, 1), 256>>>(
        cat, 512, 0, wf, 512, 0, nullptr,
        yb, 1024, 0, 16384, 1024, 512, 0);
    maxn_kernel<<<dim3(8, 16), 128>>>(yb, bf, out);
}

// round 4
// speedup vs baseline: 1.1475x; 1.0212x over previous
#include <cuda_runtime.h>
#include <math_constants.h>

// ---------------- scratch (no allocation allowed; static device globals) ----
__device__ float d_dist[16 * 1024 * 1024];   // per-layer pairwise scores (64MB)
__device__ float d_sq  [16 * 1024];          // per-point squared norms
__device__ int   d_idx [16 * 1024 * 40];     // top-40 neighbor indices
__device__ float d_pq  [16 * 1024 * 512];    // [p | q] projections (32MB)
__device__ float d_cat [16 * 1024 * 512];    // concatenated layer outputs (32MB)
__device__ float d_y   [16 * 1024 * 1024];   // final pre-max logits (64MB)
__device__ float d_wpq [512 * 128];          // transformed weights [w_L ; w_R-w_L]

static __device__ __forceinline__ unsigned long long u64max(unsigned long long a,
                                                            unsigned long long b) {
    return a > b ? a : b;
}

// ---------------- 128x128x8 double-buffered SGEMM: C = A(MxK) * B(NxK)^T ----
// mode 0: plain.  mode 1 (distance): C = (2*acc - sq[row]) - sq[col], batched.
// Requires M % 128 == 0 and N % 128 == 0 (true for all calls here).
// Microtile is split 4+4 at 64-col offset so LDS.128 fetches are conflict-free.
__global__ void __launch_bounds__(256, 2)
sgemm128(const float* __restrict__ A, int lda, long long sA,
         const float* __restrict__ B, int ldb, long long sB,
         const float* __restrict__ sq,
         float* __restrict__ C, int ldc, long long sC,
         int M, int N, int K, int mode)
{
    int bz = blockIdx.z;
    A += (long long)bz * sA;
    B += (long long)bz * sB;
    C += (long long)bz * sC;
    const float* sqb = sq ? (sq + (long long)bz * M) : nullptr;

    __shared__ float As[2][8][132];
    __shared__ float Bs[2][8][132];

    const int tid = threadIdx.x;          // 256 threads
    const int row0 = blockIdx.x * 128;
    const int col0 = blockIdx.y * 128;

    // loader: element e = tid + j*256 of the 128x8 tile; k = e&7 (fast), m = e>>3
    const int lk = tid & 7;
    const int lm = tid >> 3;              // 0..31, +32*j

    // compute: 16x16 thread grid; each thread owns rows {ty*4..+3, 64+ty*4..+3}
    // and cols {tx*4..+3, 64+tx*4..+3}
    const int tx = tid & 15;
    const int ty = tid >> 4;

    float acc[8][8];
#pragma unroll
    for (int i = 0; i < 8; i++)
#pragma unroll
        for (int j = 0; j < 8; j++) acc[i][j] = 0.f;

    float pa[4], pb[4];
    const int nk = (K + 7) >> 3;

    // prologue: load tile 0
    {
        int k = lk;
        bool ok = (k < K);
#pragma unroll
        for (int j = 0; j < 4; j++) {
            int m = lm + 32 * j;
            pa[j] = ok ? A[(long long)(row0 + m) * lda + k] : 0.f;
            pb[j] = ok ? B[(long long)(col0 + m) * ldb + k] : 0.f;
        }
#pragma unroll
        for (int j = 0; j < 4; j++) {
            As[0][lk][lm + 32 * j] = pa[j];
            Bs[0][lk][lm + 32 * j] = pb[j];
        }
    }
    __syncthreads();

    for (int t = 0; t < nk; t++) {
        int cur = t & 1;
        if (t + 1 < nk) {
            int k = (t + 1) * 8 + lk;
            bool ok = (k < K);
#pragma unroll
            for (int j = 0; j < 4; j++) {
                int m = lm + 32 * j;
                pa[j] = ok ? A[(long long)(row0 + m) * lda + k] : 0.f;
                pb[j] = ok ? B[(long long)(col0 + m) * ldb + k] : 0.f;
            }
        }
#pragma unroll
        for (int kk = 0; kk < 8; kk++) {
            float a[8], b[8];
            *(float4*)&a[0] = *(const float4*)&As[cur][kk][ty * 4];
            *(float4*)&a[4] = *(const float4*)&As[cur][kk][64 + ty * 4];
            *(float4*)&b[0] = *(const float4*)&Bs[cur][kk][tx * 4];
            *(float4*)&b[4] = *(const float4*)&Bs[cur][kk][64 + tx * 4];
#pragma unroll
            for (int i = 0; i < 8; i++)
#pragma unroll
                for (int j = 0; j < 8; j++)
                    acc[i][j] += a[i] * b[j];
        }
        if (t + 1 < nk) {
            int nxt = cur ^ 1;
#pragma unroll
            for (int j = 0; j < 4; j++) {
                As[nxt][lk][lm + 32 * j] = pa[j];
                Bs[nxt][lk][lm + 32 * j] = pb[j];
            }
        }
        __syncthreads();
    }

    // epilogue: split tile -> two float4 stores per row-half
#pragma unroll
    for (int ih = 0; ih < 2; ih++) {
#pragma unroll
        for (int i = 0; i < 4; i++) {
            int r = row0 + ih * 64 + ty * 4 + i;
            float srow = (mode == 1) ? sqb[r] : 0.f;
#pragma unroll
            for (int jh = 0; jh < 2; jh++) {
                float outv[4];
#pragma unroll
                for (int j = 0; j < 4; j++) {
                    float v = acc[ih * 4 + i][jh * 4 + j];
                    if (mode == 1)
                        v = (2.f * v - srow) - sqb[col0 + jh * 64 + tx * 4 + j];
                    outv[j] = v;
                }
                *(float4*)&C[(long long)r * ldc + col0 + jh * 64 + tx * 4] =
                    *(float4*)&outv[0];
            }
        }
    }
}

// ---------------- squared norms: one warp per point --------------------------
__global__ void sq_kernel(const float* __restrict__ H, int lda, int C,
                          float* __restrict__ SQ)
{
    int gwarp = (blockIdx.x * blockDim.x + threadIdx.x) >> 5;
    int lane = threadIdx.x & 31;
    if (gwarp >= 16 * 1024) return;
    const float* h = H + (long long)gwarp * lda;
    float s = 0.f;
    for (int c = lane; c < C; c += 32) { float v = h[c]; s += v * v; }
#pragma unroll
    for (int d = 16; d > 0; d >>= 1) s += __shfl_down_sync(0xffffffffu, s, d);
    if (lane == 0) SQ[gwarp] = s;
}

// ---------------- top-40 by iterative block argmax (ties -> lower index) ----
__global__ void topk40_kernel(const float* __restrict__ S, int* __restrict__ IDX)
{
    int row = blockIdx.x;                  // 0..16383
    const float* s = S + (long long)row * 1024;
    int tid = threadIdx.x;                 // 256 threads, 4 values each
    unsigned long long key[4];
#pragma unroll
    for (int j = 0; j < 4; j++) {
        int m = tid + j * 256;
        unsigned u = __float_as_uint(s[m]);
        u = (u & 0x80000000u) ? ~u : (u | 0x80000000u);   // order-preserving map
        key[j] = ((unsigned long long)u << 32) | (unsigned)(2047 - m);
    }
    __shared__ unsigned long long wmax[8];
    __shared__ int winner;
    int lane = tid & 31, wid = tid >> 5;

    for (int it = 0; it < 40; it++) {
        unsigned long long best = key[0];
#pragma unroll
        for (int j = 1; j < 4; j++) best = u64max(best, key[j]);
#pragma unroll
        for (int d = 16; d > 0; d >>= 1)
            best = u64max(best, __shfl_down_sync(0xffffffffu, best, d));
        if (lane == 0) wmax[wid] = best;
        __syncthreads();
        if (tid == 0) {
            unsigned long long b = wmax[0];
#pragma unroll
            for (int w = 1; w < 8; w++) b = u64max(b, wmax[w]);
            int m = 2047 - (int)(b & 0xFFFFFFFFull);
            winner = m;
            IDX[row * 40 + it] = m;
        }
        __syncthreads();
        int m = winner;
        if ((m & 255) == tid) key[m >> 8] = 0ull;   // remove winner
    }
}

// ---------------- weight transform: [w_L ; w_R - w_L] ------------------------
__global__ void wprep_kernel(const float* __restrict__ W, float* __restrict__ WPQ,
                             int Co, int C)
{
    int i = blockIdx.x * blockDim.x + threadIdx.x;
    if (i >= Co * C) return;
    int o = i / C, c = i % C;
    float wl = W[o * 2 * C + c];
    float wr = W[o * 2 * C + C + c];
    WPQ[o * C + c] = wl;
    WPQ[(Co + o) * C + c] = wr - wl;
}

// ---------------- gather-max + BN affine + LeakyReLU -------------------------
__global__ void edge_gathermax(const float* __restrict__ PQ,     // [16384][2*Co]
                               const int* __restrict__ IDX,
                               const float* __restrict__ g,
                               const float* __restrict__ bb,
                               float* __restrict__ OUT,          // cat + offset
                               int Co, int ldo)
{
    const float BN_INV = 0.9999950000374997f;  // 1/sqrt(1+1e-5)
    int pt = blockIdx.x;                       // 0..16383
    int b = pt >> 10;
    __shared__ int nb[40];
    if (threadIdx.x < 40) nb[threadIdx.x] = IDX[pt * 40 + threadIdx.x];
    __syncthreads();
    int ld = 2 * Co;
    long long bbase = (long long)(b << 10) * ld;
    for (int o = threadIdx.x; o < Co; o += blockDim.x) {
        float mx = -CUDART_INF_F, mn = CUDART_INF_F;
#pragma unroll 8
        for (int k = 0; k < 40; k++) {
            float v = PQ[bbase + (long long)nb[k] * ld + o];
            mx = fmaxf(mx, v);
            mn = fminf(mn, v);
        }
        float q  = PQ[(long long)pt * ld + Co + o];
        float gg = g[o];
        float y = (gg >= 0.f ? mx : mn) + q;     // monotone transform commutes
        y = gg * (y * BN_INV) + bb[o];
        y = y > 0.f ? y : 0.2f * y;
        OUT[(long long)pt * ldo + o] = y;
    }
}

// ---------------- final max over N (+ bias, constant over n) -----------------
__global__ void maxn_kernel(const float* __restrict__ Y, const float* __restrict__ bf,
                            float* __restrict__ OUT)
{
    int b = blockIdx.y;
    int o = blockIdx.x * blockDim.x + threadIdx.x;   // 0..1023
    const float* y = Y + ((long long)b * 1024) * 1024 + o;
    float mx = -CUDART_INF_F;
    for (int n = 0; n < 1024; n++) mx = fmaxf(mx, y[(long long)n * 1024]);
    OUT[b * 1024 + o] = mx + bf[o];
}

// ---------------- launch -----------------------------------------------------
extern "C" void kernel_launch(void* const* d_in, const int* in_sizes, int n_in,
                              void* d_out, int out_size)
{
    (void)in_sizes; (void)n_in; (void)out_size;
    const float* x  = (const float*)d_in[0];
    const float* w[4]  = {(const float*)d_in[1], (const float*)d_in[4],
                          (const float*)d_in[7], (const float*)d_in[10]};
    const float* g[4]  = {(const float*)d_in[2], (const float*)d_in[5],
                          (const float*)d_in[8], (const float*)d_in[11]};
    const float* bb[4] = {(const float*)d_in[3], (const float*)d_in[6],
                          (const float*)d_in[9], (const float*)d_in[12]};
    const float* wf = (const float*)d_in[13];
    const float* bf = (const float*)d_in[14];
    float* out = (float*)d_out;

    float *dist, *sq, *pq, *cat, *yb, *wpq; int* idx;
    cudaGetSymbolAddress((void**)&dist, d_dist);
    cudaGetSymbolAddress((void**)&sq,   d_sq);
    cudaGetSymbolAddress((void**)&idx,  d_idx);
    cudaGetSymbolAddress((void**)&pq,   d_pq);
    cudaGetSymbolAddress((void**)&cat,  d_cat);
    cudaGetSymbolAddress((void**)&yb,   d_y);
    cudaGetSymbolAddress((void**)&wpq,  d_wpq);

    const int Cs[4]   = {3, 64, 64, 128};
    const int Cos[4]  = {64, 64, 128, 256};
    const int offs[4] = {0, 64, 128, 256};  // output column offsets in cat

    for (int l = 0; l < 4; l++) {
        int C = Cs[l], Co = Cos[l];
        const float* A;
        int lda;
        if (l == 0) { A = x; lda = 3; }
        else        { A = cat + offs[l - 1]; lda = 512; }

        // 1. per-point squared norms
        sq_kernel<<<2048, 256>>>(A, lda, C, sq);
        // 2. batched pairwise score GEMM: s = 2*h.h^T - sq_n - sq_m
        sgemm128<<<dim3(8, 8, 16), 256>>>(
            A, lda, 1024LL * lda, A, lda, 1024LL * lda, sq,
            dist, 1024, 1024LL * 1024, 1024, 1024, C, 1);
        // 3. top-40 per row
        topk40_kernel<<<16384, 256>>>(dist, idx);
        // 4. weight transform
        wprep_kernel<<<(Co * C + 255) / 256, 256>>>(w[l], wpq, Co, C);
        // 5. per-point projections [p | q] = h * [w_L ; w_R-w_L]^T
        sgemm128<<<dim3(128, (2 * Co) / 128, 1), 256>>>(
            A, lda, 0, wpq, C, 0, nullptr,
            pq, 2 * Co, 0, 16384, 2 * Co, C, 0);
        // 6. gather-max over neighbors + BN + LeakyReLU -> cat slice
        edge_gathermax<<<16384, Co>>>(pq, idx, g[l], bb[l], cat + offs[l], Co, 512);
    }

    // final linear 512 -> 1024 (bias folded into max), then max over N
    sgemm128<<<dim3(128, 8, 1), 256>>>(
        cat, 512, 0, wf, 512, 0, nullptr,
        yb, 1024, 0, 16384, 1024, 512, 0);
    maxn_kernel<<<dim3(8, 16), 128>>>(yb, bf, out);
}

// round 5
// speedup vs baseline: 1.5215x; 1.3260x over previous
#include <cuda_runtime.h>
#include <math_constants.h>

// ---------------- scratch (static device globals; no allocation) ------------
__device__ float    d_dist[16 * 1024 * 1024];  // pairwise scores (64MB)
__device__ float    d_sq  [16 * 1024];
__device__ int      d_idx [16 * 1024 * 40];
__device__ float    d_pq  [16 * 1024 * 512];
__device__ float    d_cat [16 * 1024 * 512];
__device__ float    d_wpq [92160];             // all 4 layers' [w_L ; w_R-w_L]
__device__ unsigned d_gmax[16 * 1024];         // encoded running max (final)

static __device__ __forceinline__ unsigned encf(float v) {
    unsigned u = __float_as_uint(v);
    return (u & 0x80000000u) ? ~u : (u | 0x80000000u);   // order-preserving
}

// ---------------- 128x128x8 double-buffered SGEMM: C = A(MxK) * B(NxK)^T ----
// mode 0: plain store.
// mode 1: distance, SYMMETRIC: grid.x enumerates upper-tri block pairs; writes
//         C = 2*acc - sq_r - sq_c for tile and its mirror.
// mode 2: fused max: no C store; per-column block max -> atomicMax into gmax.
__global__ void __launch_bounds__(256, 2)
sgemm128(const float* __restrict__ A, int lda, long long sA,
         const float* __restrict__ B, int ldb, long long sB,
         const float* __restrict__ sq,
         float* __restrict__ C, int ldc, long long sC,
         int M, int N, int K, int mode, unsigned* __restrict__ gmax)
{
    int bz = blockIdx.z;
    A += (long long)bz * sA;
    B += (long long)bz * sB;
    C += (long long)bz * sC;
    const float* sqb = sq ? (sq + (long long)bz * M) : nullptr;

    int bi, bj;
    if (mode == 1) {                       // upper-tri pair decode
        int nb = N >> 7;
        int p = blockIdx.x;
        bi = 0;
        while (p >= nb - bi) { p -= nb - bi; bi++; }
        bj = bi + p;
    } else {
        bi = blockIdx.x; bj = blockIdx.y;
    }
    const int row0 = bi * 128;
    const int col0 = bj * 128;

    __shared__ float As[2][8][132];
    __shared__ float Bs[2][8][132];
    __shared__ unsigned scolmax[128];

    const int tid = threadIdx.x;
    const int lk = tid & 7;
    const int lm = tid >> 3;
    const int tx = tid & 15;
    const int ty = tid >> 4;

    float acc[8][8];
#pragma unroll
    for (int i = 0; i < 8; i++)
#pragma unroll
        for (int j = 0; j < 8; j++) acc[i][j] = 0.f;

    float pa[4], pb[4];
    const int nk = (K + 7) >> 3;

    {   // prologue
        int k = lk;
        bool ok = (k < K);
#pragma unroll
        for (int j = 0; j < 4; j++) {
            int m = lm + 32 * j;
            pa[j] = ok ? A[(long long)(row0 + m) * lda + k] : 0.f;
            pb[j] = ok ? B[(long long)(col0 + m) * ldb + k] : 0.f;
        }
#pragma unroll
        for (int j = 0; j < 4; j++) {
            As[0][lk][lm + 32 * j] = pa[j];
            Bs[0][lk][lm + 32 * j] = pb[j];
        }
    }
    __syncthreads();

    for (int t = 0; t < nk; t++) {
        int cur = t & 1;
        if (t + 1 < nk) {
            int k = (t + 1) * 8 + lk;
            bool ok = (k < K);
#pragma unroll
            for (int j = 0; j < 4; j++) {
                int m = lm + 32 * j;
                pa[j] = ok ? A[(long long)(row0 + m) * lda + k] : 0.f;
                pb[j] = ok ? B[(long long)(col0 + m) * ldb + k] : 0.f;
            }
        }
#pragma unroll
        for (int kk = 0; kk < 8; kk++) {
            float a[8], b[8];
            *(float4*)&a[0] = *(const float4*)&As[cur][kk][ty * 4];
            *(float4*)&a[4] = *(const float4*)&As[cur][kk][64 + ty * 4];
            *(float4*)&b[0] = *(const float4*)&Bs[cur][kk][tx * 4];
            *(float4*)&b[4] = *(const float4*)&Bs[cur][kk][64 + tx * 4];
#pragma unroll
            for (int i = 0; i < 8; i++)
#pragma unroll
                for (int j = 0; j < 8; j++)
                    acc[i][j] += a[i] * b[j];
        }
        if (t + 1 < nk) {
            int nxt = cur ^ 1;
#pragma unroll
            for (int j = 0; j < 4; j++) {
                As[nxt][lk][lm + 32 * j] = pa[j];
                Bs[nxt][lk][lm + 32 * j] = pb[j];
            }
        }
        __syncthreads();
    }

    if (mode == 2) {
        // fused max: column-max within block then atomicMax to gmax
        if (tid < 128) scolmax[tid] = 0u;
        __syncthreads();
#pragma unroll
        for (int jh = 0; jh < 2; jh++)
#pragma unroll
            for (int j = 0; j < 4; j++) {
                float m = acc[0][jh * 4 + j];
#pragma unroll
                for (int i = 1; i < 8; i++) m = fmaxf(m, acc[i][jh * 4 + j]);
                atomicMax(&scolmax[jh * 64 + tx * 4 + j], encf(m));
            }
        __syncthreads();
        if (tid < 128)
            atomicMax(&gmax[(row0 >> 10) * 1024 + col0 + tid], scolmax[tid]);
        return;
    }

    // normal tile store
#pragma unroll
    for (int ih = 0; ih < 2; ih++) {
#pragma unroll
        for (int i = 0; i < 4; i++) {
            int r = row0 + ih * 64 + ty * 4 + i;
            float srow = (mode == 1) ? sqb[r] : 0.f;
#pragma unroll
            for (int jh = 0; jh < 2; jh++) {
                float outv[4];
#pragma unroll
                for (int j = 0; j < 4; j++) {
                    float v = acc[ih * 4 + i][jh * 4 + j];
                    if (mode == 1)
                        v = (2.f * v - srow) - sqb[col0 + jh * 64 + tx * 4 + j];
                    outv[j] = v;
                }
                *(float4*)&C[(long long)r * ldc + col0 + jh * 64 + tx * 4] =
                    *(float4*)&outv[0];
            }
        }
    }

    // mirror store for symmetric distance (off-diagonal pairs only)
    if (mode == 1 && bi != bj) {
#pragma unroll
        for (int jh = 0; jh < 2; jh++)
#pragma unroll
            for (int j = 0; j < 4; j++) {
                int c = col0 + jh * 64 + tx * 4 + j;
                float sc = sqb[c];
#pragma unroll
                for (int ih = 0; ih < 2; ih++) {
                    int rb = row0 + ih * 64 + ty * 4;
                    float mv[4];
#pragma unroll
                    for (int i = 0; i < 4; i++)
                        mv[i] = (2.f * acc[ih * 4 + i][jh * 4 + j] - sqb[rb + i]) - sc;
                    *(float4*)&C[(long long)c * ldc + rb] = *(float4*)&mv[0];
                }
            }
    }
}

// ---------------- squared norms: one warp per point --------------------------
__global__ void sq_kernel(const float* __restrict__ H, int lda, int C,
                          float* __restrict__ SQ)
{
    int gwarp = (blockIdx.x * blockDim.x + threadIdx.x) >> 5;
    int lane = threadIdx.x & 31;
    if (gwarp >= 16 * 1024) return;
    const float* h = H + (long long)gwarp * lda;
    float s = 0.f;
    for (int c = lane; c < C; c += 32) { float v = h[c]; s += v * v; }
#pragma unroll
    for (int d = 16; d > 0; d >>= 1) s += __shfl_down_sync(0xffffffffu, s, d);
    if (lane == 0) SQ[gwarp] = s;
}

// ---------------- top-40: per-warp iterative argmax (REDUX) + 8-way merge ---
__global__ void topk40_kernel(const float* __restrict__ S, int* __restrict__ IDX)
{
    int row = blockIdx.x;                  // 0..16383
    const float* s = S + (long long)row * 1024;
    int tid = threadIdx.x;                 // 256 = 8 warps x 32
    int lane = tid & 31, w = tid >> 5;

    // warp w owns elements m = w*128 + j*32 + lane
    unsigned key[4];
#pragma unroll
    for (int j = 0; j < 4; j++) {
        int m = w * 128 + j * 32 + lane;
        key[j] = encf(s[m]);
    }

    __shared__ unsigned long long lists[8][40];

    for (int it = 0; it < 40; it++) {
        unsigned loc = max(max(key[0], key[1]), max(key[2], key[3]));
        unsigned best = __reduce_max_sync(0xffffffffu, loc);
        unsigned b0 = __ballot_sync(0xffffffffu, key[0] == best);
        unsigned b1 = __ballot_sync(0xffffffffu, key[1] == best);
        unsigned b2 = __ballot_sync(0xffffffffu, key[2] == best);
        unsigned b3 = __ballot_sync(0xffffffffu, key[3] == best);
        int j; unsigned bb;
        if (b0)      { j = 0; bb = b0; }
        else if (b1) { j = 1; bb = b1; }
        else if (b2) { j = 2; bb = b2; }
        else         { j = 3; bb = b3; }
        int wlane = __ffs(bb) - 1;
        int m = w * 128 + j * 32 + wlane;           // smallest m among ties
        if (lane == wlane) {
#pragma unroll
            for (int jj = 0; jj < 4; jj++) if (jj == j) key[jj] = 0u;
        }
        if (lane == 0)
            lists[w][it] = ((unsigned long long)best << 32) | (unsigned)(2047 - m);
    }
    __syncthreads();

    if (tid == 0) {
        unsigned long long head[8];
        int pos[8];
#pragma unroll
        for (int q = 0; q < 8; q++) { head[q] = lists[q][0]; pos[q] = 0; }
        for (int it = 0; it < 40; it++) {
            unsigned long long best = head[0];
#pragma unroll
            for (int q = 1; q < 8; q++) if (head[q] > best) best = head[q];
            IDX[row * 40 + it] = 2047 - (int)(best & 0xFFFFFFFFull);
#pragma unroll
            for (int q = 0; q < 8; q++)
                if (head[q] == best) {
                    pos[q]++;
                    head[q] = (pos[q] < 40) ? lists[q][pos[q]] : 0ull;
                }
        }
    }
}

// ---------------- weight transform: [w_L ; w_R - w_L] ------------------------
__global__ void wprep_kernel(const float* __restrict__ W, float* __restrict__ WPQ,
                             int Co, int C)
{
    int i = blockIdx.x * blockDim.x + threadIdx.x;
    if (i >= Co * C) return;
    int o = i / C, c = i % C;
    float wl = W[o * 2 * C + c];
    float wr = W[o * 2 * C + C + c];
    WPQ[o * C + c] = wl;
    WPQ[(Co + o) * C + c] = wr - wl;
}

// ---------------- gather-max + BN affine + LeakyReLU -------------------------
__global__ void edge_gathermax(const float* __restrict__ PQ,     // [16384][2*Co]
                               const int* __restrict__ IDX,
                               const float* __restrict__ g,
                               const float* __restrict__ bb,
                               float* __restrict__ OUT,          // cat + offset
                               int Co, int ldo)
{
    const float BN_INV = 0.9999950000374997f;  // 1/sqrt(1+1e-5)
    int pt = blockIdx.x;
    int b = pt >> 10;
    __shared__ int nb[40];
    if (threadIdx.x < 40) nb[threadIdx.x] = IDX[pt * 40 + threadIdx.x];
    __syncthreads();
    int ld = 2 * Co;
    long long bbase = (long long)(b << 10) * ld;
    for (int o = threadIdx.x; o < Co; o += blockDim.x) {
        float mx = -CUDART_INF_F, mn = CUDART_INF_F;
#pragma unroll 8
        for (int k = 0; k < 40; k++) {
            float v = PQ[bbase + (long long)nb[k] * ld + o];
            mx = fmaxf(mx, v);
            mn = fminf(mn, v);
        }
        float q  = PQ[(long long)pt * ld + Co + o];
        float gg = g[o];
        float y = (gg >= 0.f ? mx : mn) + q;
        y = gg * (y * BN_INV) + bb[o];
        y = y > 0.f ? y : 0.2f * y;
        OUT[(long long)pt * ldo + o] = y;
    }
}

// ---------------- gmax init / decode ----------------------------------------
__global__ void gmax_init(unsigned* __restrict__ g)
{
    g[blockIdx.x * 1024 + threadIdx.x] = 0u;
}

__global__ void decode_out(const unsigned* __restrict__ g,
                           const float* __restrict__ bf, float* __restrict__ out)
{
    int i = blockIdx.x * 256 + threadIdx.x;   // 16384
    unsigned e = g[i];
    unsigned u = (e & 0x80000000u) ? (e ^ 0x80000000u) : ~e;
    out[i] = __uint_as_float(u) + bf[i & 1023];
}

// ---------------- launch -----------------------------------------------------
extern "C" void kernel_launch(void* const* d_in, const int* in_sizes, int n_in,
                              void* d_out, int out_size)
{
    (void)in_sizes; (void)n_in; (void)out_size;
    const float* x  = (const float*)d_in[0];
    const float* w[4]  = {(const float*)d_in[1], (const float*)d_in[4],
                          (const float*)d_in[7], (const float*)d_in[10]};
    const float* g[4]  = {(const float*)d_in[2], (const float*)d_in[5],
                          (const float*)d_in[8], (const float*)d_in[11]};
    const float* bb[4] = {(const float*)d_in[3], (const float*)d_in[6],
                          (const float*)d_in[9], (const float*)d_in[12]};
    const float* wf = (const float*)d_in[13];
    const float* bf = (const float*)d_in[14];
    float* out = (float*)d_out;

    float *dist, *sq, *pq, *cat, *wpq; int* idx; unsigned* gm;
    cudaGetSymbolAddress((void**)&dist, d_dist);
    cudaGetSymbolAddress((void**)&sq,   d_sq);
    cudaGetSymbolAddress((void**)&idx,  d_idx);
    cudaGetSymbolAddress((void**)&pq,   d_pq);
    cudaGetSymbolAddress((void**)&cat,  d_cat);
    cudaGetSymbolAddress((void**)&wpq,  d_wpq);
    cudaGetSymbolAddress((void**)&gm,   d_gmax);

    const int Cs[4]   = {3, 64, 64, 128};
    const int Cos[4]  = {64, 64, 128, 256};
    const int offs[4] = {0, 64, 128, 256};     // cat column offsets
    const int woff[4] = {0, 1024, 9216, 25600};// wpq offsets per layer

    // [0] final-max accumulator init
    gmax_init<<<16, 1024>>>(gm);

    for (int l = 0; l < 4; l++) {
        int C = Cs[l], Co = Cos[l];
        const float* A;
        int lda;
        if (l == 0) { A = x; lda = 3; }
        else        { A = cat + offs[l - 1]; lda = 512; }

        // per-point squared norms
        sq_kernel<<<2048, 256>>>(A, lda, C, sq);
        if (l == 0) wprep_kernel<<<1, 256>>>(w[0], wpq + woff[0], 64, 3);
        // symmetric pairwise score GEMM (36 upper-tri block pairs x 16 batches)
        sgemm128<<<dim3(36, 1, 16), 256>>>(
            A, lda, 1024LL * lda, A, lda, 1024LL * lda, sq,
            dist, 1024, 1024LL * 1024, 1024, 1024, C, 1, nullptr);
        if (l == 0) wprep_kernel<<<(64 * 64 + 255) / 256, 256>>>(w[1], wpq + woff[1], 64, 64);
        // top-40 per row
        topk40_kernel<<<16384, 256>>>(dist, idx);
        if (l == 0) wprep_kernel<<<(128 * 64 + 255) / 256, 256>>>(w[2], wpq + woff[2], 128, 64);
        // per-point projections [p | q]
        sgemm128<<<dim3(128, (2 * Co) / 128, 1), 256>>>(
            A, lda, 0, wpq + woff[l], C, 0, nullptr,
            pq, 2 * Co, 0, 16384, 2 * Co, C, 0, nullptr);
        if (l == 0) wprep_kernel<<<(256 * 128 + 255) / 256, 256>>>(w[3], wpq + woff[3], 256, 128);
        // gather-max over neighbors + BN + LeakyReLU -> cat slice
        edge_gathermax<<<16384, Co>>>(pq, idx, g[l], bb[l], cat + offs[l], Co, 512);
    }

    // final linear 512 -> 1024 fused with max over N (atomicMax into gm)
    sgemm128<<<dim3(128, 8, 1), 256>>>(
        cat, 512, 0, wf, 512, 0, nullptr,
        nullptr, 0, 0, 16384, 1024, 512, 2, gm);
    decode_out<<<64, 256>>>(gm, bf, out);
}

// round 7
// speedup vs baseline: 1.5683x; 1.0307x over previous
#include <cuda_runtime.h>
#include <math_constants.h>
#include <cstdint>

// ---------------- scratch (static device globals; no allocation) ------------
__device__ float    d_dist[16 * 1024 * 1024];  // pairwise scores (64MB)
__device__ float    d_sq  [16 * 1024];
__device__ int      d_idx [16 * 1024 * 40];
__device__ float    d_pq  [16 * 1024 * 512];
__device__ float    d_cat [16 * 1024 * 512];
__device__ float    d_wpq [92160];             // all 4 layers' [w_L ; w_R-w_L]
__device__ unsigned d_gmax[16 * 1024];         // encoded running max (final)

static __device__ __forceinline__ unsigned encf(float v) {
    unsigned u = __float_as_uint(v);
    return (u & 0x80000000u) ? ~u : (u | 0x80000000u);   // order-preserving
}

// ============== final GEMM on tensor cores via mma.sync tf32x3 ==============
// Y[m][n] = sum_k A[m][k] * B[n][k];  A=cat(16384x512), B=wf(1024x512).
// 3-pass split: AhBh + AlBh + AhBl (fp32 accum). Fused max over m -> gmax.
static __device__ __forceinline__ void cvt_split(float v, uint32_t& h, uint32_t& l) {
    asm("cvt.rna.tf32.f32 %0, %1;" : "=r"(h) : "f"(v));
    float hf = __uint_as_float(h);
    float r = v - hf;
    asm("cvt.rna.tf32.f32 %0, %1;" : "=r"(l) : "f"(r));
}
static __device__ __forceinline__ void mma_tf32(float* c, uint32_t a0, uint32_t a1,
                                                uint32_t a2, uint32_t a3,
                                                uint32_t b0, uint32_t b1) {
    asm volatile(
        "mma.sync.aligned.m16n8k8.row.col.f32.tf32.tf32.f32 "
        "{%0,%1,%2,%3}, {%4,%5,%6,%7}, {%8,%9}, {%0,%1,%2,%3};"
        : "+f"(c[0]), "+f"(c[1]), "+f"(c[2]), "+f"(c[3])
        : "r"(a0), "r"(a1), "r"(a2), "r"(a3), "r"(b0), "r"(b1));
}

static constexpr int HG_STRIDE = 24;   // smem row stride (words), bank-clean
static constexpr int HG_ARR = 128 * HG_STRIDE;
static constexpr int HG_SMEM = 4 * HG_ARR * 4;   // 49152 bytes

// storage permutation within a 16-wide K chunk: pairs [t, t+4] adjacent
static __device__ __forceinline__ int sidx(int k) {
    int ks = k >> 3, kk = k & 7;
    return ks * 8 + ((kk & 3) << 1) + (kk >> 2);
}

__global__ void __launch_bounds__(256, 2)
hgemm_tf32(const float* __restrict__ A, const float* __restrict__ B,
           unsigned* __restrict__ gmax)
{
    extern __shared__ uint32_t dsm[];
    uint32_t* Ah = dsm;
    uint32_t* Al = Ah + HG_ARR;
    uint32_t* Bh = Al + HG_ARR;
    uint32_t* Bl = Bh + HG_ARR;

    const int tid = threadIdx.x;
    const int wid = tid >> 5, lane = tid & 31;
    const int wr = wid >> 2, wc = wid & 3;     // warp 2x4 grid
    const int g = lane >> 2, t = lane & 3;
    const int row0 = blockIdx.x * 128;         // M tile
    const int col0 = blockIdx.y * 128;         // N tile

    float acc[4][4][4];
#pragma unroll
    for (int mt = 0; mt < 4; mt++)
#pragma unroll
        for (int nt = 0; nt < 4; nt++)
#pragma unroll
            for (int i = 0; i < 4; i++) acc[mt][nt][i] = 0.f;

    const int lrow = tid >> 2;                 // 0..63 (+64 on i=1)
    const int lc4 = tid & 3;

    for (int chunk = 0; chunk < 32; chunk++) {
        const int k0 = chunk * 16;
        __syncthreads();
#pragma unroll
        for (int i = 0; i < 2; i++) {
            int row = i * 64 + lrow;
            float4 va = *(const float4*)&A[(size_t)(row0 + row) * 512 + k0 + lc4 * 4];
            float4 vb = *(const float4*)&B[(size_t)(col0 + row) * 512 + k0 + lc4 * 4];
            float ea[4] = {va.x, va.y, va.z, va.w};
            float eb[4] = {vb.x, vb.y, vb.z, vb.w};
#pragma unroll
            for (int j = 0; j < 4; j++) {
                int s = sidx(lc4 * 4 + j);
                uint32_t h, l;
                cvt_split(ea[j], h, l);
                Ah[row * HG_STRIDE + s] = h;
                Al[row * HG_STRIDE + s] = l;
                cvt_split(eb[j], h, l);
                Bh[row * HG_STRIDE + s] = h;
                Bl[row * HG_STRIDE + s] = l;
            }
        }
        __syncthreads();

        const uint32_t* pAs[3] = {Ah, Al, Ah};
        const uint32_t* pBs[3] = {Bh, Bh, Bl};
#pragma unroll
        for (int pass = 0; pass < 3; pass++) {
            const uint32_t* pA = pAs[pass];
            const uint32_t* pB = pBs[pass];
#pragma unroll
            for (int ks = 0; ks < 2; ks++) {
                uint32_t af[4][4];
#pragma unroll
                for (int mt = 0; mt < 4; mt++) {
                    int rbase = wr * 64 + mt * 16 + g;
                    uint2 a02 = *(const uint2*)&pA[rbase * HG_STRIDE + ks * 8 + 2 * t];
                    uint2 a13 = *(const uint2*)&pA[(rbase + 8) * HG_STRIDE + ks * 8 + 2 * t];
                    af[mt][0] = a02.x; af[mt][1] = a13.x;
                    af[mt][2] = a02.y; af[mt][3] = a13.y;
                }
#pragma unroll
                for (int nt = 0; nt < 4; nt++) {
                    int nbase = wc * 32 + nt * 8 + g;
                    uint2 bb = *(const uint2*)&pB[nbase * HG_STRIDE + ks * 8 + 2 * t];
#pragma unroll
                    for (int mt = 0; mt < 4; mt++)
                        mma_tf32(acc[mt][nt], af[mt][0], af[mt][1], af[mt][2],
                                 af[mt][3], bb.x, bb.y);
                }
            }
        }
    }

    // fused max over the CTA's 128 rows (all in one batch), atomicMax to gmax
    const int batch = row0 >> 10;
#pragma unroll
    for (int nt = 0; nt < 4; nt++) {
#pragma unroll
        for (int j = 0; j < 2; j++) {
            float v = -CUDART_INF_F;
#pragma unroll
            for (int mt = 0; mt < 4; mt++)
                v = fmaxf(v, fmaxf(acc[mt][nt][j], acc[mt][nt][j + 2]));
#pragma unroll
            for (int off = 4; off < 32; off <<= 1)
                v = fmaxf(v, __shfl_xor_sync(0xffffffffu, v, off));
            if (lane < 4) {
                int col = col0 + wc * 32 + nt * 8 + 2 * lane + j;
                atomicMax(&gmax[batch * 1024 + col], encf(v));
            }
        }
    }
}

// ---------------- 128x128x8 double-buffered SGEMM: C = A(MxK) * B(NxK)^T ----
// mode 0: plain store.
// mode 1: distance, SYMMETRIC upper-tri pairs, writes tile + mirror.
__global__ void __launch_bounds__(256, 2)
sgemm128(const float* __restrict__ A, int lda, long long sA,
         const float* __restrict__ B, int ldb, long long sB,
         const float* __restrict__ sq,
         float* __restrict__ C, int ldc, long long sC,
         int M, int N, int K, int mode)
{
    int bz = blockIdx.z;
    A += (long long)bz * sA;
    B += (long long)bz * sB;
    C += (long long)bz * sC;
    const float* sqb = sq ? (sq + (long long)bz * M) : nullptr;

    int bi, bj;
    if (mode == 1) {
        int nb = N >> 7;
        int p = blockIdx.x;
        bi = 0;
        while (p >= nb - bi) { p -= nb - bi; bi++; }
        bj = bi + p;
    } else {
        bi = blockIdx.x; bj = blockIdx.y;
    }
    const int row0 = bi * 128;
    const int col0 = bj * 128;

    __shared__ float As[2][8][132];
    __shared__ float Bs[2][8][132];

    const int tid = threadIdx.x;
    const int lk = tid & 7;
    const int lm = tid >> 3;
    const int tx = tid & 15;
    const int ty = tid >> 4;

    float acc[8][8];
#pragma unroll
    for (int i = 0; i < 8; i++)
#pragma unroll
        for (int j = 0; j < 8; j++) acc[i][j] = 0.f;

    float pa[4], pb[4];
    const int nk = (K + 7) >> 3;

    {   // prologue
        int k = lk;
        bool ok = (k < K);
#pragma unroll
        for (int j = 0; j < 4; j++) {
            int m = lm + 32 * j;
            pa[j] = ok ? A[(long long)(row0 + m) * lda + k] : 0.f;
            pb[j] = ok ? B[(long long)(col0 + m) * ldb + k] : 0.f;
        }
#pragma unroll
        for (int j = 0; j < 4; j++) {
            As[0][lk][lm + 32 * j] = pa[j];
            Bs[0][lk][lm + 32 * j] = pb[j];
        }
    }
    __syncthreads();

    for (int t = 0; t < nk; t++) {
        int cur = t & 1;
        if (t + 1 < nk) {
            int k = (t + 1) * 8 + lk;
            bool ok = (k < K);
#pragma unroll
            for (int j = 0; j < 4; j++) {
                int m = lm + 32 * j;
                pa[j] = ok ? A[(long long)(row0 + m) * lda + k] : 0.f;
                pb[j] = ok ? B[(long long)(col0 + m) * ldb + k] : 0.f;
            }
        }
#pragma unroll
        for (int kk = 0; kk < 8; kk++) {
            float a[8], b[8];
            *(float4*)&a[0] = *(const float4*)&As[cur][kk][ty * 4];
            *(float4*)&a[4] = *(const float4*)&As[cur][kk][64 + ty * 4];
            *(float4*)&b[0] = *(const float4*)&Bs[cur][kk][tx * 4];
            *(float4*)&b[4] = *(const float4*)&Bs[cur][kk][64 + tx * 4];
#pragma unroll
            for (int i = 0; i < 8; i++)
#pragma unroll
                for (int j = 0; j < 8; j++)
                    acc[i][j] += a[i] * b[j];
        }
        if (t + 1 < nk) {
            int nxt = cur ^ 1;
#pragma unroll
            for (int j = 0; j < 4; j++) {
                As[nxt][lk][lm + 32 * j] = pa[j];
                Bs[nxt][lk][lm + 32 * j] = pb[j];
            }
        }
        __syncthreads();
    }

#pragma unroll
    for (int ih = 0; ih < 2; ih++) {
#pragma unroll
        for (int i = 0; i < 4; i++) {
            int r = row0 + ih * 64 + ty * 4 + i;
            float srow = (mode == 1) ? sqb[r] : 0.f;
#pragma unroll
            for (int jh = 0; jh < 2; jh++) {
                float outv[4];
#pragma unroll
                for (int j = 0; j < 4; j++) {
                    float v = acc[ih * 4 + i][jh * 4 + j];
                    if (mode == 1)
                        v = (2.f * v - srow) - sqb[col0 + jh * 64 + tx * 4 + j];
                    outv[j] = v;
                }
                *(float4*)&C[(long long)r * ldc + col0 + jh * 64 + tx * 4] =
                    *(float4*)&outv[0];
            }
        }
    }

    if (mode == 1 && bi != bj) {
#pragma unroll
        for (int jh = 0; jh < 2; jh++)
#pragma unroll
            for (int j = 0; j < 4; j++) {
                int c = col0 + jh * 64 + tx * 4 + j;
                float sc = sqb[c];
#pragma unroll
                for (int ih = 0; ih < 2; ih++) {
                    int rb = row0 + ih * 64 + ty * 4;
                    float mv[4];
#pragma unroll
                    for (int i = 0; i < 4; i++)
                        mv[i] = (2.f * acc[ih * 4 + i][jh * 4 + j] - sqb[rb + i]) - sc;
                    *(float4*)&C[(long long)c * ldc + rb] = *(float4*)&mv[0];
                }
            }
    }
}

// ---------------- squared norms ---------------------------------------------
__global__ void sq_kernel(const float* __restrict__ H, int lda, int C,
                          float* __restrict__ SQ)
{
    int gwarp = (blockIdx.x * blockDim.x + threadIdx.x) >> 5;
    int lane = threadIdx.x & 31;
    if (gwarp >= 16 * 1024) return;
    const float* h = H + (long long)gwarp * lda;
    float s = 0.f;
    for (int c = lane; c < C; c += 32) { float v = h[c]; s += v * v; }
#pragma unroll
    for (int d = 16; d > 0; d >>= 1) s += __shfl_down_sync(0xffffffffu, s, d);
    if (lane == 0) SQ[gwarp] = s;
}

// ---------------- top-40: per-warp iterative argmax (REDUX) + 8-way merge ---
__global__ void topk40_kernel(const float* __restrict__ S, int* __restrict__ IDX)
{
    int row = blockIdx.x;
    const float* s = S + (long long)row * 1024;
    int tid = threadIdx.x;                 // 256 = 8 warps x 32
    int lane = tid & 31, w = tid >> 5;

    unsigned key[4];
#pragma unroll
    for (int j = 0; j < 4; j++) {
        int m = w * 128 + j * 32 + lane;
        key[j] = encf(s[m]);
    }

    __shared__ unsigned long long lists[8][40];

    for (int it = 0; it < 40; it++) {
        unsigned loc = max(max(key[0], key[1]), max(key[2], key[3]));
        unsigned best = __reduce_max_sync(0xffffffffu, loc);
        unsigned b0 = __ballot_sync(0xffffffffu, key[0] == best);
        unsigned b1 = __ballot_sync(0xffffffffu, key[1] == best);
        unsigned b2 = __ballot_sync(0xffffffffu, key[2] == best);
        unsigned b3 = __ballot_sync(0xffffffffu, key[3] == best);
        int j; unsigned bb;
        if (b0)      { j = 0; bb = b0; }
        else if (b1) { j = 1; bb = b1; }
        else if (b2) { j = 2; bb = b2; }
        else         { j = 3; bb = b3; }
        int wlane = __ffs(bb) - 1;
        int m = w * 128 + j * 32 + wlane;
        if (lane == wlane) {
#pragma unroll
            for (int jj = 0; jj < 4; jj++) if (jj == j) key[jj] = 0u;
        }
        if (lane == 0)
            lists[w][it] = ((unsigned long long)best << 32) | (unsigned)(2047 - m);
    }
    __syncthreads();

    if (tid == 0) {
        unsigned long long head[8];
        int pos[8];
#pragma unroll
        for (int q = 0; q < 8; q++) { head[q] = lists[q][0]; pos[q] = 0; }
        for (int it = 0; it < 40; it++) {
            unsigned long long best = head[0];
#pragma unroll
            for (int q = 1; q < 8; q++) if (head[q] > best) best = head[q];
            IDX[row * 40 + it] = 2047 - (int)(best & 0xFFFFFFFFull);
#pragma unroll
            for (int q = 0; q < 8; q++)
                if (head[q] == best) {
                    pos[q]++;
                    head[q] = (pos[q] < 40) ? lists[q][pos[q]] : 0ull;
                }
        }
    }
}

// ---------------- weight transform ------------------------------------------
__global__ void wprep_kernel(const float* __restrict__ W, float* __restrict__ WPQ,
                             int Co, int C)
{
    int i = blockIdx.x * blockDim.x + threadIdx.x;
    if (i >= Co * C) return;
    int o = i / C, c = i % C;
    float wl = W[o * 2 * C + c];
    float wr = W[o * 2 * C + C + c];
    WPQ[o * C + c] = wl;
    WPQ[(Co + o) * C + c] = wr - wl;
}

// ---------------- gather-max + BN affine + LeakyReLU ------------------------
__global__ void edge_gathermax(const float* __restrict__ PQ,
                               const int* __restrict__ IDX,
                               const float* __restrict__ g,
                               const float* __restrict__ bb,
                               float* __restrict__ OUT,
                               int Co, int ldo)
{
    const float BN_INV = 0.9999950000374997f;
    int pt = blockIdx.x;
    int b = pt >> 10;
    __shared__ int nb[40];
    if (threadIdx.x < 40) nb[threadIdx.x] = IDX[pt * 40 + threadIdx.x];
    __syncthreads();
    int ld = 2 * Co;
    long long bbase = (long long)(b << 10) * ld;
    for (int o = threadIdx.x; o < Co; o += blockDim.x) {
        float mx = -CUDART_INF_F, mn = CUDART_INF_F;
#pragma unroll 8
        for (int k = 0; k < 40; k++) {
            float v = PQ[bbase + (long long)nb[k] * ld + o];
            mx = fmaxf(mx, v);
            mn = fminf(mn, v);
        }
        float q  = PQ[(long long)pt * ld + Co + o];
        float gg = g[o];
        float y = (gg >= 0.f ? mx : mn) + q;
        y = gg * (y * BN_INV) + bb[o];
        y = y > 0.f ? y : 0.2f * y;
        OUT[(long long)pt * ldo + o] = y;
    }
}

// ---------------- gmax init / decode ----------------------------------------
__global__ void gmax_init(unsigned* __restrict__ g)
{
    g[blockIdx.x * 1024 + threadIdx.x] = 0u;
}

__global__ void decode_out(const unsigned* __restrict__ g,
                           const float* __restrict__ bf, float* __restrict__ out)
{
    int i = blockIdx.x * 256 + threadIdx.x;   // 16384
    unsigned e = g[i];
    unsigned u = (e & 0x80000000u) ? (e ^ 0x80000000u) : ~e;
    out[i] = __uint_as_float(u) + bf[i & 1023];
}

// ---------------- launch -----------------------------------------------------
extern "C" void kernel_launch(void* const* d_in, const int* in_sizes, int n_in,
                              void* d_out, int out_size)
{
    (void)in_sizes; (void)n_in; (void)out_size;
    const float* x  = (const float*)d_in[0];
    const float* w[4]  = {(const float*)d_in[1], (const float*)d_in[4],
                          (const float*)d_in[7], (const float*)d_in[10]};
    const float* g[4]  = {(const float*)d_in[2], (const float*)d_in[5],
                          (const float*)d_in[8], (const float*)d_in[11]};
    const float* bb[4] = {(const float*)d_in[3], (const float*)d_in[6],
                          (const float*)d_in[9], (const float*)d_in[12]};
    const float* wf = (const float*)d_in[13];
    const float* bf = (const float*)d_in[14];
    float* out = (float*)d_out;

    float *dist, *sq, *pq, *cat, *wpq; int* idx; unsigned* gm;
    cudaGetSymbolAddress((void**)&dist, d_dist);
    cudaGetSymbolAddress((void**)&sq,   d_sq);
    cudaGetSymbolAddress((void**)&idx,  d_idx);
    cudaGetSymbolAddress((void**)&pq,   d_pq);
    cudaGetSymbolAddress((void**)&cat,  d_cat);
    cudaGetSymbolAddress((void**)&wpq,  d_wpq);
    cudaGetSymbolAddress((void**)&gm,   d_gmax);

    cudaFuncSetAttribute(hgemm_tf32, cudaFuncAttributeMaxDynamicSharedMemorySize,
                         HG_SMEM);

    const int Cs[4]   = {3, 64, 64, 128};
    const int Cos[4]  = {64, 64, 128, 256};
    const int offs[4] = {0, 64, 128, 256};
    const int woff[4] = {0, 1024, 9216, 25600};

    gmax_init<<<16, 1024>>>(gm);

    for (int l = 0; l < 4; l++) {
        int C = Cs[l], Co = Cos[l];
        const float* A;
        int lda;
        if (l == 0) { A = x; lda = 3; }
        else        { A = cat + offs[l - 1]; lda = 512; }

        sq_kernel<<<2048, 256>>>(A, lda, C, sq);
        if (l == 0) wprep_kernel<<<1, 256>>>(w[0], wpq + woff[0], 64, 3);
        sgemm128<<<dim3(36, 1, 16), 256>>>(
            A, lda, 1024LL * lda, A, lda, 1024LL * lda, sq,
            dist, 1024, 1024LL * 1024, 1024, 1024, C, 1);
        if (l == 0) wprep_kernel<<<(64 * 64 + 255) / 256, 256>>>(w[1], wpq + woff[1], 64, 64);
        topk40_kernel<<<16384, 256>>>(dist, idx);
        if (l == 0) wprep_kernel<<<(128 * 64 + 255) / 256, 256>>>(w[2], wpq + woff[2], 128, 64);
        sgemm128<<<dim3(128, (2 * Co) / 128, 1), 256>>>(
            A, lda, 0, wpq + woff[l], C, 0, nullptr,
            pq, 2 * Co, 0, 16384, 2 * Co, C, 0);
        if (l == 0) wprep_kernel<<<(256 * 128 + 255) / 256, 256>>>(w[3], wpq + woff[3], 256, 128);
        edge_gathermax<<<16384, Co>>>(pq, idx, g[l], bb[l], cat + offs[l], Co, 512);
    }

    // final linear 512 -> 1024 on tensor cores (tf32x3), fused max over N
    hgemm_tf32<<<dim3(128, 8), 256, HG_SMEM>>>(cat, wf, gm);
    decode_out<<<64, 256>>>(gm, bf, out);
}